// round 2
// baseline (speedup 1.0000x reference)
#include <cuda_runtime.h>
#include <math.h>

// Problem constants
#define BSZ 32
#define CCH 128
#define HH  32
#define WW  32
#define HWP (HH*WW)            // 1024
#define LL  (CCH*HWP)          // 131072 per batch
#define NTOT (BSZ*LL)          // 4194304
#define MMH 5                  // Anderson history
#define LAMREG 1e-4f
#define TOLV 1e-5f
#define ALPHA_D 0.9f

// ---------------- device state (no runtime allocation allowed) ----------------
__device__ float g_Z[MMH][NTOT];      // X history
__device__ float g_F[MMH][NTOT];      // Fh history
__device__ float g_S[BSZ][MMH][MMH];  // Gram matrix (incrementally maintained, symmetric)
__device__ float g_alpha[BSZ][MMH];
__device__ float g_resden;
__device__ int   g_flag;              // converged flag
__device__ int   g_outslot;           // slot of last executed body
__device__ float g_Wt[CCH*9*CCH];     // transposed weights: [(ci*9 + ky*3 + kx)*128 + co]

// ---------------- small kernels ----------------

__global__ void prep_w(const float* __restrict__ W) {
    int i = blockIdx.x * blockDim.x + threadIdx.x;
    if (i >= CCH * CCH * 9) return;
    int co = i / (CCH * 9);
    int r  = i % (CCH * 9);
    int ci = r / 9;
    int t  = r % 9;
    g_Wt[(ci * 9 + t) * CCH + co] = W[i];
}

__global__ void init_state() {
    int t = threadIdx.x;
    if (t == 0) { g_flag = 0; g_outslot = 0; g_resden = 0.f; }
    for (int i = t; i < BSZ * MMH * MMH; i += blockDim.x) ((float*)g_S)[i] = 0.f;
    for (int i = t; i < BSZ * MMH; i += blockDim.x) ((float*)g_alpha)[i] = 0.f;
}

__global__ void fill_z0() {
    int i = blockIdx.x * blockDim.x + threadIdx.x;   // over NTOT/4
    const float v = 1.0f / 128.0f;
    ((float4*)g_Z[0])[i] = make_float4(v, v, v, v);
}

// xnew = sum_{j<n} alpha_j * F[j]  ->  Z[s]
__global__ void update_x(int s, int n) {
    if (g_flag) return;
    int i4 = blockIdx.x * blockDim.x + threadIdx.x;  // over NTOT/4
    int b = i4 / (LL / 4);
    float a[MMH];
#pragma unroll
    for (int j = 0; j < MMH; j++) a[j] = g_alpha[b][j];
    float4 acc = make_float4(0.f, 0.f, 0.f, 0.f);
    for (int j = 0; j < n; j++) {
        float4 f = ((const float4*)g_F[j])[i4];
        acc.x = fmaf(a[j], f.x, acc.x);
        acc.y = fmaf(a[j], f.y, acc.y);
        acc.z = fmaf(a[j], f.z, acc.z);
        acc.w = fmaf(a[j], f.w, acc.w);
    }
    ((float4*)g_Z[s])[i4] = acc;
}

// Solve the masked (m+1)x(m+1) system per batch; 32 threads, 1 block.
__global__ void solve_k(int k) {
    if (g_flag) return;
    int b = threadIdx.x;
    if (b >= BSZ) return;
    int n = k < MMH ? k : MMH;
    int s = k % MMH;
    float A[6][6], rv[6];
    A[0][0] = 0.f;
    for (int j = 0; j < MMH; j++) {
        float a = (j < n) ? 1.f : 0.f;
        A[0][j + 1] = a; A[j + 1][0] = a;
    }
    for (int i = 0; i < MMH; i++)
        for (int j = 0; j < MMH; j++) {
            float v;
            if (i < n && j < n) v = g_S[b][i][j] + ((i == j) ? LAMREG : 0.f);
            else                v = (i == j) ? 1.f : 0.f;
            A[i + 1][j + 1] = v;
        }
    for (int i = 0; i < 6; i++) rv[i] = 0.f;
    rv[0] = 1.f;
    // Gaussian elimination with partial pivoting
    for (int c = 0; c < 6; c++) {
        int p = c; float mx = fabsf(A[c][c]);
        for (int r = c + 1; r < 6; r++) { float t = fabsf(A[r][c]); if (t > mx) { mx = t; p = r; } }
        if (p != c) {
            for (int q = c; q < 6; q++) { float t = A[c][q]; A[c][q] = A[p][q]; A[p][q] = t; }
            float t = rv[c]; rv[c] = rv[p]; rv[p] = t;
        }
        float inv = 1.f / A[c][c];
        for (int r = c + 1; r < 6; r++) {
            float f = A[r][c] * inv;
            if (f != 0.f) {
                for (int q = c + 1; q < 6; q++) A[r][q] -= f * A[c][q];
                rv[r] -= f * rv[c];
            }
        }
    }
    float xs[6];
    for (int c = 5; c >= 0; c--) {
        float t = rv[c];
        for (int q = c + 1; q < 6; q++) t -= A[c][q] * xs[q];
        xs[c] = t / A[c][c];
    }
    for (int j = 0; j < MMH; j++) g_alpha[b][j] = (j < n) ? xs[j + 1] : 0.f;
    // zero Gram row/col s for the upcoming refill by the f-kernel epilogue
    for (int j = 0; j < MMH; j++) { g_S[b][s][j] = 0.f; g_S[b][j][s] = 0.f; }
}

__global__ void check_k(int k) {
    if (g_flag) return;
    int s = k % MMH;
    float rn = 0.f;
    for (int b = 0; b < BSZ; b++) rn += g_S[b][s][s];   // sum_b ||g_s||^2 = resnum
    float res = sqrtf(rn) / (1e-5f + sqrtf(g_resden));
    g_outslot = s;
    if (res < TOLV) g_flag = 1;
    g_resden = 0.f;
}

__global__ void final_copy(float* __restrict__ out) {
    int i4 = blockIdx.x * blockDim.x + threadIdx.x;  // over NTOT/4
    int sl = g_outslot;
    ((float4*)out)[i4] = ((const float4*)g_F[sl])[i4];
}

// ---------------- fused f-evaluation kernel ----------------
// Computes fnew = softmax_ch((1-a)*z + a*(Conv3x3(mask-inject(z)) + bias)),
// writes F[s] (and optionally Z[out2slot]), and in the epilogue incrementally
// updates Gram row/col s plus the residual denominator.
// Block = (y, b), 256 threads. Thread tile: 4 out-channels x 4 pixels.

#define SWID 36
#define SMEM_FLOATS (3 * CCH * SWID)
#define SMEM_BYTES (SMEM_FLOATS * 4)

__device__ __forceinline__ float warpReduceSum(float v) {
#pragma unroll
    for (int o = 16; o > 0; o >>= 1) v += __shfl_xor_sync(0xFFFFFFFF, v, o);
    return v;
}

__global__ void f_eval(int s, int out2slot, int nact, int do_res,
                       const float* __restrict__ xg, const int* __restrict__ maskg,
                       const float* __restrict__ bias) {
    if (g_flag) return;
    extern __shared__ float sm[];
    __shared__ float sMax[WW], sInv[WW], sW8[8];

    const int y = blockIdx.x;
    const int b = blockIdx.y;
    const int tid = threadIdx.x;
    const float* __restrict__ zin = g_Z[s];
    float* __restrict__ fout = g_F[s];
    float* __restrict__ out2 = (out2slot >= 0) ? g_Z[out2slot] : nullptr;

    // ---- stage masked input rows (y-1, y, y+1) into smem with 1-col halo ----
    for (int i = tid; i < 3 * CCH; i += 256) { sm[i * SWID + 0] = 0.f; sm[i * SWID + 33] = 0.f; }
    for (int i = tid; i < 3 * CCH * WW; i += 256) {
        int ky = i / (CCH * WW);
        int r  = i % (CCH * WW);
        int ci = r / WW;
        int x  = r % WW;
        int yy = y + ky - 1;
        float v = 0.f;
        if (yy >= 0 && yy < HH) {
            int zi = ((b * CCH + ci) * HH + yy) * WW + x;
            float z = zin[zi];
            int mf = maskg[(b * HH + yy) * WW + x];
            v = mf ? xg[zi] : z;
        }
        sm[(ky * CCH + ci) * SWID + x + 1] = v;
    }
    __syncthreads();

    // ---- conv 3x3: each thread does 4 co x 4 x ----
    const int x0 = (tid & 7) * 4;
    const int c0 = (tid >> 3) * 4;
    float acc[4][4];
#pragma unroll
    for (int c = 0; c < 4; c++)
#pragma unroll
        for (int xx = 0; xx < 4; xx++) acc[c][xx] = 0.f;

    for (int ci = 0; ci < CCH; ci++) {
#pragma unroll
        for (int ky = 0; ky < 3; ky++) {
            const float* zr = &sm[(ky * CCH + ci) * SWID + x0];
            float4 za = *(const float4*)zr;
            float2 zb = *(const float2*)(zr + 4);
            float zv[6] = { za.x, za.y, za.z, za.w, zb.x, zb.y };
            const float* wp = &g_Wt[(ci * 9 + ky * 3) * CCH + c0];
#pragma unroll
            for (int kx = 0; kx < 3; kx++) {
                float4 w = *(const float4*)(wp + kx * CCH);
                float wv[4] = { w.x, w.y, w.z, w.w };
#pragma unroll
                for (int c = 0; c < 4; c++)
#pragma unroll
                    for (int xx = 0; xx < 4; xx++)
                        acc[c][xx] = fmaf(wv[c], zv[xx + kx], acc[c][xx]);
            }
        }
    }

    // raw z for the damping term (pre = (1-a)*z + a*(lin+bias))
    float zq[4][4];
#pragma unroll
    for (int c = 0; c < 4; c++) {
        float4 t = *(const float4*)&zin[((b * CCH + c0 + c) * HH + y) * WW + x0];
        zq[c][0] = t.x; zq[c][1] = t.y; zq[c][2] = t.z; zq[c][3] = t.w;
    }
    float bi[4];
#pragma unroll
    for (int c = 0; c < 4; c++) bi[c] = bias[c0 + c];

    __syncthreads();          // done reading sm; reuse as pre[128][33]
    float* sPre = sm;
    const float c1 = 1.0f - ALPHA_D;
#pragma unroll
    for (int c = 0; c < 4; c++)
#pragma unroll
        for (int xx = 0; xx < 4; xx++)
            sPre[(c0 + c) * 33 + x0 + xx] = c1 * zq[c][xx] + ALPHA_D * (acc[c][xx] + bi[c]);
    __syncthreads();

    // ---- softmax stats per pixel (8 warps, 4 pixels each) ----
    {
        int w = tid >> 5, lane = tid & 31;
        for (int xx = w; xx < WW; xx += 8) {
            float m = -1e30f;
#pragma unroll
            for (int i = 0; i < 4; i++) m = fmaxf(m, sPre[(lane + 32 * i) * 33 + xx]);
#pragma unroll
            for (int o = 16; o > 0; o >>= 1) m = fmaxf(m, __shfl_xor_sync(0xFFFFFFFF, m, o));
            float ss = 0.f;
#pragma unroll
            for (int i = 0; i < 4; i++) ss += __expf(sPre[(lane + 32 * i) * 33 + xx] - m);
            ss = warpReduceSum(ss);
            if (lane == 0) { sMax[xx] = m; sInv[xx] = 1.0f / ss; }
        }
    }
    __syncthreads();

    // ---- output + fused Gram/residual epilogue ----
    const int x = tid & 31;
    const int cc0 = tid >> 5;
    float dots[MMH] = { 0.f, 0.f, 0.f, 0.f, 0.f };
    float resd = 0.f;
    for (int c = cc0; c < CCH; c += 8) {
        int idx = ((b * CCH + c) * HH + y) * WW + x;
        float val = __expf(sPre[c * 33 + x] - sMax[x]) * sInv[x];
        fout[idx] = val;
        if (out2) out2[idx] = val;
        float zi = zin[idx];
        float gs = val - zi;
#pragma unroll
        for (int j = 0; j < MMH; j++) {
            if (j < nact) {
                float gj = (j == s) ? gs : (g_F[j][idx] - g_Z[j][idx]);
                dots[j] = fmaf(gs, gj, dots[j]);
            }
        }
        resd = fmaf(val, val, resd);
    }

    // block-reduce the (<=6) scalars, then atomics
    int lane = tid & 31, w = tid >> 5;
#pragma unroll
    for (int j = 0; j < MMH; j++) {
        if (j >= nact) continue;
        float v = warpReduceSum(dots[j]);
        if (lane == 0) sW8[w] = v;
        __syncthreads();
        if (tid == 0) {
            float t = 0.f;
#pragma unroll
            for (int i = 0; i < 8; i++) t += sW8[i];
            atomicAdd(&g_S[b][s][j], t);
            if (j != s) atomicAdd(&g_S[b][j][s], t);
        }
        __syncthreads();
    }
    if (do_res) {
        float v = warpReduceSum(resd);
        if (lane == 0) sW8[w] = v;
        __syncthreads();
        if (tid == 0) {
            float t = 0.f;
#pragma unroll
            for (int i = 0; i < 8; i++) t += sW8[i];
            atomicAdd(&g_resden, t);
        }
    }
}

// ---------------- host orchestration (graph-capturable) ----------------
extern "C" void kernel_launch(void* const* d_in, const int* in_sizes, int n_in,
                              void* d_out, int out_size) {
    // robust input matching by element count
    const float* x = nullptr; const float* W = nullptr;
    const float* bias = nullptr; const int* mask = nullptr;
    for (int i = 0; i < n_in; i++) {
        switch (in_sizes[i]) {
            case 4194304: x    = (const float*)d_in[i]; break;
            case 147456:  W    = (const float*)d_in[i]; break;
            case 128:     bias = (const float*)d_in[i]; break;
            case 32768:   mask = (const int*)d_in[i];   break;
        }
    }
    float* out = (float*)d_out;

    cudaFuncSetAttribute(f_eval, cudaFuncAttributeMaxDynamicSharedMemorySize, SMEM_BYTES);

    dim3 fgrid(HH, BSZ);
    const int NB4 = NTOT / 4 / 256;   // 4096 blocks for elementwise float4 kernels

    prep_w<<<(CCH * CCH * 9 + 255) / 256, 256>>>(W);
    init_state<<<1, 256>>>();
    fill_z0<<<NB4, 256>>>();

    // F0 = f(z0); also Z[1] = F0.   (s=0, nact=1 -> fills S[0][0])
    f_eval<<<fgrid, 256, SMEM_BYTES>>>(0, 1, 1, 0, x, mask, bias);
    // F1 = f(F0).                   (s=1, nact=2 -> fills S[1][0..1])
    f_eval<<<fgrid, 256, SMEM_BYTES>>>(1, -1, 2, 0, x, mask, bias);

    for (int k = 2; k < 50; k++) {
        int s = k % MMH;
        int n = (k < MMH) ? k : MMH;
        int nactE = (k + 1 < MMH) ? (k + 1) : MMH;
        solve_k<<<1, 32>>>(k);
        update_x<<<NB4, 256>>>(s, n);
        f_eval<<<fgrid, 256, SMEM_BYTES>>>(s, -1, nactE, 1, x, mask, bias);
        check_k<<<1, 1>>>(k);
    }

    final_copy<<<NB4, 256>>>(out);
    (void)out_size;
}

// round 3
// speedup vs baseline: 1.0207x; 1.0207x over previous
#include <cuda_runtime.h>
#include <math.h>

// Problem constants
#define BSZ 32
#define CCH 128
#define HH  32
#define WW  32
#define HWP (HH*WW)            // 1024
#define LL  (CCH*HWP)          // 131072 per batch
#define NTOT (BSZ*LL)          // 4194304
#define MMH 5                  // Anderson history
#define LAMREG 1e-4f
#define TOLV 1e-5f
#define ALPHA_D 0.9f

// ---------------- device state (no runtime allocation allowed) ----------------
__device__ float g_Z[MMH][NTOT];      // X history
__device__ float g_F[MMH][NTOT];      // Fh history
__device__ float g_S[BSZ][MMH][MMH];  // Gram matrix (incrementally maintained, symmetric)
__device__ float g_alpha[BSZ][MMH];
__device__ float g_resden;
__device__ int   g_flag;              // converged flag
__device__ int   g_outslot;           // slot of last executed body
__device__ float g_Wt[CCH*9*CCH];     // transposed weights: [(ci*9 + ky*3 + kx)*128 + co]

// ---------------- small kernels ----------------

__global__ void prep_w(const float* __restrict__ W) {
    int i = blockIdx.x * blockDim.x + threadIdx.x;
    if (i >= CCH * CCH * 9) return;
    int co = i / (CCH * 9);
    int r  = i % (CCH * 9);
    int ci = r / 9;
    int t  = r % 9;
    g_Wt[(ci * 9 + t) * CCH + co] = W[i];
}

__global__ void init_state() {
    int t = threadIdx.x;
    if (t == 0) { g_flag = 0; g_outslot = 0; g_resden = 0.f; }
    for (int i = t; i < BSZ * MMH * MMH; i += blockDim.x) ((float*)g_S)[i] = 0.f;
    for (int i = t; i < BSZ * MMH; i += blockDim.x) ((float*)g_alpha)[i] = 0.f;
}

__global__ void fill_z0() {
    int i = blockIdx.x * blockDim.x + threadIdx.x;   // over NTOT/4
    const float v = 1.0f / 128.0f;
    ((float4*)g_Z[0])[i] = make_float4(v, v, v, v);
}

// xnew = sum_{j<n} alpha_j * F[j]  ->  Z[s]
__global__ void update_x(int s, int n) {
    if (g_flag) return;
    int i4 = blockIdx.x * blockDim.x + threadIdx.x;  // over NTOT/4
    int b = i4 / (LL / 4);
    float a[MMH];
#pragma unroll
    for (int j = 0; j < MMH; j++) a[j] = g_alpha[b][j];
    float4 acc = make_float4(0.f, 0.f, 0.f, 0.f);
    for (int j = 0; j < n; j++) {
        float4 f = ((const float4*)g_F[j])[i4];
        acc.x = fmaf(a[j], f.x, acc.x);
        acc.y = fmaf(a[j], f.y, acc.y);
        acc.z = fmaf(a[j], f.z, acc.z);
        acc.w = fmaf(a[j], f.w, acc.w);
    }
    ((float4*)g_Z[s])[i4] = acc;
}

// Solve the masked (m+1)x(m+1) system per batch; 32 threads, 1 block.
__global__ void solve_k(int k) {
    if (g_flag) return;
    int b = threadIdx.x;
    if (b >= BSZ) return;
    int n = k < MMH ? k : MMH;
    int s = k % MMH;
    float A[6][6], rv[6];
    A[0][0] = 0.f;
    for (int j = 0; j < MMH; j++) {
        float a = (j < n) ? 1.f : 0.f;
        A[0][j + 1] = a; A[j + 1][0] = a;
    }
    for (int i = 0; i < MMH; i++)
        for (int j = 0; j < MMH; j++) {
            float v;
            if (i < n && j < n) v = g_S[b][i][j] + ((i == j) ? LAMREG : 0.f);
            else                v = (i == j) ? 1.f : 0.f;
            A[i + 1][j + 1] = v;
        }
    for (int i = 0; i < 6; i++) rv[i] = 0.f;
    rv[0] = 1.f;
    // Gaussian elimination with partial pivoting
    for (int c = 0; c < 6; c++) {
        int p = c; float mx = fabsf(A[c][c]);
        for (int r = c + 1; r < 6; r++) { float t = fabsf(A[r][c]); if (t > mx) { mx = t; p = r; } }
        if (p != c) {
            for (int q = c; q < 6; q++) { float t = A[c][q]; A[c][q] = A[p][q]; A[p][q] = t; }
            float t = rv[c]; rv[c] = rv[p]; rv[p] = t;
        }
        float inv = 1.f / A[c][c];
        for (int r = c + 1; r < 6; r++) {
            float f = A[r][c] * inv;
            if (f != 0.f) {
                for (int q = c + 1; q < 6; q++) A[r][q] -= f * A[c][q];
                rv[r] -= f * rv[c];
            }
        }
    }
    float xs[6];
    for (int c = 5; c >= 0; c--) {
        float t = rv[c];
        for (int q = c + 1; q < 6; q++) t -= A[c][q] * xs[q];
        xs[c] = t / A[c][c];
    }
    for (int j = 0; j < MMH; j++) g_alpha[b][j] = (j < n) ? xs[j + 1] : 0.f;
    // zero Gram row/col s for the upcoming refill by the f-kernel epilogue
    for (int j = 0; j < MMH; j++) { g_S[b][s][j] = 0.f; g_S[b][j][s] = 0.f; }
}

__global__ void check_k(int k) {
    if (g_flag) return;
    int s = k % MMH;
    float rn = 0.f;
    for (int b = 0; b < BSZ; b++) rn += g_S[b][s][s];   // sum_b ||g_s||^2 = resnum
    float res = sqrtf(rn) / (1e-5f + sqrtf(g_resden));
    g_outslot = s;
    if (res < TOLV) g_flag = 1;
    g_resden = 0.f;
}

__global__ void final_copy(float* __restrict__ out) {
    int i4 = blockIdx.x * blockDim.x + threadIdx.x;  // over NTOT/4
    int sl = g_outslot;
    ((float4*)out)[i4] = ((const float4*)g_F[sl])[i4];
}

// ---------------- fused f-evaluation kernel ----------------
// Computes fnew = softmax_ch((1-a)*z + a*(Conv3x3(mask-inject(z)) + bias)),
// writes F[s] (and optionally Z[out2slot]), and in the epilogue incrementally
// updates Gram row/col s plus the residual denominator.
// Block = (y, b), 256 threads. Thread tile: 4 out-channels x 4 pixels.

#define SWID 36
#define SMEM_FLOATS (3 * CCH * SWID)
#define SMEM_BYTES (SMEM_FLOATS * 4)

__device__ __forceinline__ float warpReduceSum(float v) {
#pragma unroll
    for (int o = 16; o > 0; o >>= 1) v += __shfl_xor_sync(0xFFFFFFFF, v, o);
    return v;
}

__global__ void f_eval(int s, int out2slot, int nact, int do_res,
                       const float* __restrict__ xg, const int* __restrict__ maskg,
                       const float* __restrict__ bias) {
    if (g_flag) return;
    extern __shared__ float sm[];
    __shared__ float sMax[WW], sInv[WW], sW8[8];

    const int y = blockIdx.x;
    const int b = blockIdx.y;
    const int tid = threadIdx.x;
    const float* __restrict__ zin = g_Z[s];
    float* __restrict__ fout = g_F[s];
    float* __restrict__ out2 = (out2slot >= 0) ? g_Z[out2slot] : nullptr;

    // ---- stage masked input rows (y-1, y, y+1) into smem with 1-col halo ----
    for (int i = tid; i < 3 * CCH; i += 256) { sm[i * SWID + 0] = 0.f; sm[i * SWID + 33] = 0.f; }
    for (int i = tid; i < 3 * CCH * WW; i += 256) {
        int ky = i / (CCH * WW);
        int r  = i % (CCH * WW);
        int ci = r / WW;
        int x  = r % WW;
        int yy = y + ky - 1;
        float v = 0.f;
        if (yy >= 0 && yy < HH) {
            int zi = ((b * CCH + ci) * HH + yy) * WW + x;
            float z = zin[zi];
            int mf = maskg[(b * HH + yy) * WW + x];
            v = mf ? xg[zi] : z;
        }
        sm[(ky * CCH + ci) * SWID + x + 1] = v;
    }
    __syncthreads();

    // ---- conv 3x3: each thread does 4 co x 4 x ----
    const int x0 = (tid & 7) * 4;
    const int c0 = (tid >> 3) * 4;
    float acc[4][4];
#pragma unroll
    for (int c = 0; c < 4; c++)
#pragma unroll
        for (int xx = 0; xx < 4; xx++) acc[c][xx] = 0.f;

    for (int ci = 0; ci < CCH; ci++) {
#pragma unroll
        for (int ky = 0; ky < 3; ky++) {
            const float* zr = &sm[(ky * CCH + ci) * SWID + x0];
            float4 za = *(const float4*)zr;
            float2 zb = *(const float2*)(zr + 4);
            float zv[6] = { za.x, za.y, za.z, za.w, zb.x, zb.y };
            const float* wp = &g_Wt[(ci * 9 + ky * 3) * CCH + c0];
#pragma unroll
            for (int kx = 0; kx < 3; kx++) {
                float4 w = *(const float4*)(wp + kx * CCH);
                float wv[4] = { w.x, w.y, w.z, w.w };
#pragma unroll
                for (int c = 0; c < 4; c++)
#pragma unroll
                    for (int xx = 0; xx < 4; xx++)
                        acc[c][xx] = fmaf(wv[c], zv[xx + kx], acc[c][xx]);
            }
        }
    }

    // raw z for the damping term (pre = (1-a)*z + a*(lin+bias))
    float zq[4][4];
#pragma unroll
    for (int c = 0; c < 4; c++) {
        float4 t = *(const float4*)&zin[((b * CCH + c0 + c) * HH + y) * WW + x0];
        zq[c][0] = t.x; zq[c][1] = t.y; zq[c][2] = t.z; zq[c][3] = t.w;
    }
    float bi[4];
#pragma unroll
    for (int c = 0; c < 4; c++) bi[c] = bias[c0 + c];

    __syncthreads();          // done reading sm; reuse as pre[128][33]
    float* sPre = sm;
    const float c1 = 1.0f - ALPHA_D;
#pragma unroll
    for (int c = 0; c < 4; c++)
#pragma unroll
        for (int xx = 0; xx < 4; xx++)
            sPre[(c0 + c) * 33 + x0 + xx] = c1 * zq[c][xx] + ALPHA_D * (acc[c][xx] + bi[c]);
    __syncthreads();

    // ---- softmax stats per pixel (8 warps, 4 pixels each) ----
    {
        int w = tid >> 5, lane = tid & 31;
        for (int xx = w; xx < WW; xx += 8) {
            float m = -1e30f;
#pragma unroll
            for (int i = 0; i < 4; i++) m = fmaxf(m, sPre[(lane + 32 * i) * 33 + xx]);
#pragma unroll
            for (int o = 16; o > 0; o >>= 1) m = fmaxf(m, __shfl_xor_sync(0xFFFFFFFF, m, o));
            float ss = 0.f;
#pragma unroll
            for (int i = 0; i < 4; i++) ss += __expf(sPre[(lane + 32 * i) * 33 + xx] - m);
            ss = warpReduceSum(ss);
            if (lane == 0) { sMax[xx] = m; sInv[xx] = 1.0f / ss; }
        }
    }
    __syncthreads();

    // ---- output + fused Gram/residual epilogue ----
    const int x = tid & 31;
    const int cc0 = tid >> 5;
    float dots[MMH] = { 0.f, 0.f, 0.f, 0.f, 0.f };
    float resd = 0.f;
    for (int c = cc0; c < CCH; c += 8) {
        int idx = ((b * CCH + c) * HH + y) * WW + x;
        float val = __expf(sPre[c * 33 + x] - sMax[x]) * sInv[x];
        fout[idx] = val;
        if (out2) out2[idx] = val;
        float zi = zin[idx];
        float gs = val - zi;
#pragma unroll
        for (int j = 0; j < MMH; j++) {
            if (j < nact) {
                float gj = (j == s) ? gs : (g_F[j][idx] - g_Z[j][idx]);
                dots[j] = fmaf(gs, gj, dots[j]);
            }
        }
        resd = fmaf(val, val, resd);
    }

    // block-reduce the (<=6) scalars, then atomics
    int lane = tid & 31, w = tid >> 5;
#pragma unroll
    for (int j = 0; j < MMH; j++) {
        if (j >= nact) continue;
        float v = warpReduceSum(dots[j]);
        if (lane == 0) sW8[w] = v;
        __syncthreads();
        if (tid == 0) {
            float t = 0.f;
#pragma unroll
            for (int i = 0; i < 8; i++) t += sW8[i];
            atomicAdd(&g_S[b][s][j], t);
            if (j != s) atomicAdd(&g_S[b][j][s], t);
        }
        __syncthreads();
    }
    if (do_res) {
        float v = warpReduceSum(resd);
        if (lane == 0) sW8[w] = v;
        __syncthreads();
        if (tid == 0) {
            float t = 0.f;
#pragma unroll
            for (int i = 0; i < 8; i++) t += sW8[i];
            atomicAdd(&g_resden, t);
        }
    }
}

// ---------------- host orchestration (graph-capturable) ----------------
extern "C" void kernel_launch(void* const* d_in, const int* in_sizes, int n_in,
                              void* d_out, int out_size) {
    // robust input matching by element count
    const float* x = nullptr; const float* W = nullptr;
    const float* bias = nullptr; const int* mask = nullptr;
    for (int i = 0; i < n_in; i++) {
        switch (in_sizes[i]) {
            case 4194304: x    = (const float*)d_in[i]; break;
            case 147456:  W    = (const float*)d_in[i]; break;
            case 128:     bias = (const float*)d_in[i]; break;
            case 32768:   mask = (const int*)d_in[i];   break;
        }
    }
    float* out = (float*)d_out;

    cudaFuncSetAttribute(f_eval, cudaFuncAttributeMaxDynamicSharedMemorySize, SMEM_BYTES);

    dim3 fgrid(HH, BSZ);
    const int NB4 = NTOT / 4 / 256;   // 4096 blocks for elementwise float4 kernels

    prep_w<<<(CCH * CCH * 9 + 255) / 256, 256>>>(W);
    init_state<<<1, 256>>>();
    fill_z0<<<NB4, 256>>>();

    // F0 = f(z0); also Z[1] = F0.   (s=0, nact=1 -> fills S[0][0])
    f_eval<<<fgrid, 256, SMEM_BYTES>>>(0, 1, 1, 0, x, mask, bias);
    // F1 = f(F0).                   (s=1, nact=2 -> fills S[1][0..1])
    f_eval<<<fgrid, 256, SMEM_BYTES>>>(1, -1, 2, 0, x, mask, bias);

    for (int k = 2; k < 50; k++) {
        int s = k % MMH;
        int n = (k < MMH) ? k : MMH;
        int nactE = (k + 1 < MMH) ? (k + 1) : MMH;
        solve_k<<<1, 32>>>(k);
        update_x<<<NB4, 256>>>(s, n);
        f_eval<<<fgrid, 256, SMEM_BYTES>>>(s, -1, nactE, 1, x, mask, bias);
        check_k<<<1, 1>>>(k);
    }

    final_copy<<<NB4, 256>>>(out);
    (void)out_size;
}

// round 5
// speedup vs baseline: 2.1651x; 2.1211x over previous
#include <cuda_runtime.h>
#include <cuda_bf16.h>
#include <math.h>
#include <stdint.h>

#define BSZ 32
#define CCH 128
#define HH  32
#define WW  32
#define HWP (HH*WW)
#define LL  (CCH*HWP)
#define NTOT (BSZ*LL)
#define MMH 5
#define LAMREG 1e-4f
#define TOLV 1e-5f

// ---------------- device state ----------------
__device__ float g_Z[MMH][NTOT];
__device__ float g_F[MMH][NTOT];
__device__ float g_S[BSZ][MMH][MMH];
__device__ float g_alpha[BSZ][MMH];
__device__ float g_resden;
__device__ int   g_flag;
__device__ int   g_outslot;
// A fragments, per-lane order: [kstep 72][warp 8][lane 32] x uint4 (a0..a3, bf16x2 each)
__device__ uint4 g_Wf0[72 * 256];   // big split
__device__ uint4 g_Wf1[72 * 256];   // small split

// ---------------- helpers ----------------
__device__ __forceinline__ uint32_t smem_u32(const void* p) {
    uint32_t a;
    asm("{ .reg .u64 t; cvta.to.shared.u64 t, %1; cvt.u32.u64 %0, t; }" : "=r"(a) : "l"(p));
    return a;
}
__device__ __forceinline__ uint32_t pk2(float a, float b) {
    __nv_bfloat162 t = __floats2bfloat162_rn(a, b);
    return *reinterpret_cast<uint32_t*>(&t);
}
__device__ __forceinline__ float warpReduceSum(float v) {
#pragma unroll
    for (int o = 16; o > 0; o >>= 1) v += __shfl_xor_sync(0xFFFFFFFF, v, o);
    return v;
}

#define LDMX4(r0, r1, r2, r3, addr) \
    asm volatile("ldmatrix.sync.aligned.m8n8.x4.shared.b16 {%0,%1,%2,%3}, [%4];" \
        : "=r"(r0), "=r"(r1), "=r"(r2), "=r"(r3) : "r"(addr))

#define MMA(d, a, b0_, b1_) \
    asm volatile("mma.sync.aligned.m16n8k16.row.col.f32.bf16.bf16.f32 " \
        "{%0,%1,%2,%3}, {%4,%5,%6,%7}, {%8,%9}, {%0,%1,%2,%3};" \
        : "+f"((d)[0]), "+f"((d)[1]), "+f"((d)[2]), "+f"((d)[3]) \
        : "r"((a).x), "r"((a).y), "r"((a).z), "r"((a).w), "r"(b0_), "r"(b1_))

// ---------------- smem layout (bytes) ----------------
// Bsm: [split 2][r 4][xi 34][ci 128 (pad to 136)] bf16 : row stride 272B
#define BSM_ROWB   272
#define BSM_RSTR   (34 * BSM_ROWB)          // 9248 per (split,r)
#define BSM_SPLIT  (4 * BSM_RSTR)           // 36992
#define BSM_BYTES  (2 * BSM_SPLIT)          // 73984
#define SPRE_B     BSM_BYTES                // 2 planes x 128 x 33 f32 = 33792
#define PMAX_B     (SPRE_B + 33792)
#define PINV_B     (PMAX_B + 256)
#define PRED_B     (PINV_B + 256)
#define SMEM_TOTAL (PRED_B + 64)

// ---------------- small kernels ----------------
__global__ void prep_w(const float* __restrict__ W) {
    int t = blockIdx.x * 256 + threadIdx.x;
    if (t >= 72 * 256) return;
    int s = t >> 8, rem = t & 255, w = rem >> 5, l = rem & 31;
    int ky = s / 24, kx = (s / 8) % 3, cig = s & 7;
    int m0 = w * 16 + (l >> 2);
    int k0 = cig * 16 + (l & 3) * 2;
    uint32_t big[4], sml[4];
#pragma unroll
    for (int jc = 0; jc < 2; jc++)
#pragma unroll
        for (int jr = 0; jr < 2; jr++) {
            int reg = jc * 2 + jr;                  // a0,a1,a2,a3
            int co = m0 + jr * 8;
            int ci = k0 + jc * 8;
            float wa = W[((co * CCH + ci) * 3 + ky) * 3 + kx];
            float wb = W[((co * CCH + ci + 1) * 3 + ky) * 3 + kx];
            __nv_bfloat16 ba = __float2bfloat16(wa);
            __nv_bfloat16 bb = __float2bfloat16(wb);
            float ra = wa - __bfloat162float(ba);
            float rb = wb - __bfloat162float(bb);
            big[reg] = pk2(wa, wb);
            sml[reg] = pk2(ra, rb);
        }
    g_Wf0[t] = make_uint4(big[0], big[1], big[2], big[3]);
    g_Wf1[t] = make_uint4(sml[0], sml[1], sml[2], sml[3]);
}

__global__ void init_state() {
    int t = threadIdx.x;
    if (t == 0) { g_flag = 0; g_outslot = 0; g_resden = 0.f; }
    for (int i = t; i < BSZ * MMH * MMH; i += blockDim.x) ((float*)g_S)[i] = 0.f;
    for (int i = t; i < BSZ * MMH; i += blockDim.x) ((float*)g_alpha)[i] = 0.f;
}

__global__ void fill_z0() {
    int i = blockIdx.x * blockDim.x + threadIdx.x;
    const float v = 1.0f / 128.0f;
    ((float4*)g_Z[0])[i] = make_float4(v, v, v, v);
}

__global__ void update_x(int s, int n) {
    if (g_flag) return;
    int t = blockIdx.x * 256 + threadIdx.x;
    for (int i4 = t; i4 < NTOT / 4; i4 += 512 * 256) {
        int b = i4 / (LL / 4);
        float4 acc = make_float4(0.f, 0.f, 0.f, 0.f);
        for (int j = 0; j < n; j++) {
            float a = g_alpha[b][j];
            float4 f = ((const float4*)g_F[j])[i4];
            acc.x = fmaf(a, f.x, acc.x); acc.y = fmaf(a, f.y, acc.y);
            acc.z = fmaf(a, f.z, acc.z); acc.w = fmaf(a, f.w, acc.w);
        }
        ((float4*)g_Z[s])[i4] = acc;
    }
}

__device__ __forceinline__ void solve_body(int b, int k) {
    int n = k < MMH ? k : MMH;
    int s = k % MMH;
    float A[6][6], rv[6];
    A[0][0] = 0.f;
    for (int j = 0; j < MMH; j++) {
        float a = (j < n) ? 1.f : 0.f;
        A[0][j + 1] = a; A[j + 1][0] = a;
    }
    for (int i = 0; i < MMH; i++)
        for (int j = 0; j < MMH; j++) {
            float v;
            if (i < n && j < n) v = g_S[b][i][j] + ((i == j) ? LAMREG : 0.f);
            else                v = (i == j) ? 1.f : 0.f;
            A[i + 1][j + 1] = v;
        }
    for (int i = 0; i < 6; i++) rv[i] = 0.f;
    rv[0] = 1.f;
    for (int c = 0; c < 6; c++) {
        int p = c; float mx = fabsf(A[c][c]);
        for (int r = c + 1; r < 6; r++) { float t = fabsf(A[r][c]); if (t > mx) { mx = t; p = r; } }
        if (p != c) {
            for (int q = c; q < 6; q++) { float t = A[c][q]; A[c][q] = A[p][q]; A[p][q] = t; }
            float t = rv[c]; rv[c] = rv[p]; rv[p] = t;
        }
        float inv = 1.f / A[c][c];
        for (int r = c + 1; r < 6; r++) {
            float f = A[r][c] * inv;
            if (f != 0.f) {
                for (int q = c + 1; q < 6; q++) A[r][q] -= f * A[c][q];
                rv[r] -= f * rv[c];
            }
        }
    }
    float xs[6];
    for (int c = 5; c >= 0; c--) {
        float t = rv[c];
        for (int q = c + 1; q < 6; q++) t -= A[c][q] * xs[q];
        xs[c] = t / A[c][c];
    }
    for (int j = 0; j < MMH; j++) g_alpha[b][j] = (j < n) ? xs[j + 1] : 0.f;
    for (int j = 0; j < MMH; j++) { g_S[b][s][j] = 0.f; g_S[b][j][s] = 0.f; }
}

__global__ void solve_k(int k) {
    if (g_flag) return;
    if (threadIdx.x < BSZ) solve_body(threadIdx.x, k);
}

__global__ void check_solve(int k) {
    if (g_flag) return;
    __shared__ int sconv;
    int b = threadIdx.x;
    int s = k % MMH;
    if (b == 0) {
        float rn = 0.f;
        for (int bb = 0; bb < BSZ; bb++) rn += g_S[bb][s][s];
        float res = sqrtf(rn) / (1e-5f + sqrtf(g_resden));
        g_outslot = s;
        sconv = (res < TOLV) ? 1 : 0;
        g_resden = 0.f;
        if (sconv) g_flag = 1;
    }
    __syncthreads();
    if (sconv || k + 1 >= 50) return;
    if (b < BSZ) solve_body(b, k + 1);
}

__global__ void final_copy(float* __restrict__ out) {
    int i4 = blockIdx.x * blockDim.x + threadIdx.x;
    int sl = g_outslot;
    ((float4*)out)[i4] = ((const float4*)g_F[sl])[i4];
}

// ---------------- mma.sync f-evaluation ----------------
// Block = (y-pair, b), 256 threads (8 warps). Warp w: co stripe [16w,16w+16), both rows.
__global__ void __launch_bounds__(256, 2)
f_eval(int slot, int out2slot, int nact, int do_res,
       const float* __restrict__ xg, const int* __restrict__ maskg,
       const float* __restrict__ bias) {
    if (g_flag) return;
    extern __shared__ float sm[];
    const uint32_t smb = smem_u32(sm);
    const int tid = threadIdx.x;
    const int w = tid >> 5, lane = tid & 31;
    const int y0 = blockIdx.x * 2;
    const int b  = blockIdx.y;
    const float* __restrict__ zin = g_Z[slot];
    float* __restrict__ fout = g_F[slot];
    float* __restrict__ out2 = (out2slot >= 0) ? g_Z[out2slot] : nullptr;

    // ---- zero halo columns (xi = 0 and 33) of Bsm ----
    for (int i = tid; i < 2 * 4 * 2 * (BSM_ROWB / 4); i += 256) {
        int word = i % (BSM_ROWB / 4);
        int rr = i / (BSM_ROWB / 4);        // 0..15: split*8 + r*2 + (xi?0:33)
        int split = rr >> 3; int r = (rr >> 1) & 3; int xi = (rr & 1) ? 33 : 0;
        ((uint32_t*)((char*)sm + split * BSM_SPLIT + r * BSM_RSTR + xi * BSM_ROWB))[word] = 0;
    }

    // ---- stage B: warp w -> (r = w&3, cihalf = w>>2); lane = x ----
    {
        int r = w & 3, cihalf = w >> 2;
        int r_img = y0 + r - 1;
        bool valid = (r_img >= 0 && r_img < HH);
        char* dst0 = (char*)sm + r * BSM_RSTR + (lane + 1) * BSM_ROWB + cihalf * 128;
        char* dst1 = dst0 + BSM_SPLIT;
        if (valid) {
            int m = maskg[(b * HH + r_img) * WW + lane];
            const float* src = (m ? xg : zin) + ((b * CCH + cihalf * 64) * HH + r_img) * WW + lane;
#pragma unroll 4
            for (int ci = 0; ci < 64; ci += 2) {
                float va = src[ci * HWP];
                float vb = src[(ci + 1) * HWP];
                __nv_bfloat16 ba = __float2bfloat16(va), bb = __float2bfloat16(vb);
                *(uint32_t*)(dst0 + ci * 2) = pk2(va, vb);
                *(uint32_t*)(dst1 + ci * 2) = pk2(va - __bfloat162float(ba), vb - __bfloat162float(bb));
            }
        } else {
            for (int ci = 0; ci < 64; ci += 2) {
                *(uint32_t*)(dst0 + ci * 2) = 0;
                *(uint32_t*)(dst1 + ci * 2) = 0;
            }
        }
    }
    __syncthreads();

    // ---- conv: 72 k-steps, bf16x3 ----
    float acc[2][16];
#pragma unroll
    for (int r = 0; r < 2; r++)
#pragma unroll
        for (int i = 0; i < 16; i++) acc[r][i] = 0.f;

    const int fragidx = w * 32 + lane;
    uint4 A0 = g_Wf0[fragidx];
    uint4 A1 = g_Wf1[fragidx];
    const int mi = lane >> 3;
    const int khalf = mi & 1;
    const uint32_t xrow = (uint32_t)((mi >> 1) * 8 + (lane & 7));   // row within n-tile pair

    for (int s = 0; s < 72; s++) {
        uint4 nA0, nA1;
        if (s < 71) { nA0 = g_Wf0[(s + 1) * 256 + fragidx]; nA1 = g_Wf1[(s + 1) * 256 + fragidx]; }
        int ky = s / 24, kxc = (s / 8) % 3, cig = s & 7;
        uint32_t cioff = (uint32_t)(cig * 32 + khalf * 16);
#pragma unroll
        for (int row = 0; row < 2; row++) {
            uint32_t base0 = smb + (uint32_t)((row + ky) * BSM_RSTR);
#pragma unroll
            for (int p = 0; p < 2; p++) {
                uint32_t xoff = (p * 16 + xrow) * 8u + (uint32_t)kxc;   // ntile*8 + (lane&7) + kxc
                // note: ntile = 2p + (mi>>1) -> xoff = (2p+(mi>>1))*8 + (lane&7) + kxc
                uint32_t aoff = ((p * 2 + (mi >> 1)) * 8 + (lane & 7) + kxc) * BSM_ROWB + cioff;
                (void)xoff;
                uint32_t ab = base0 + aoff;
                uint32_t bb0, bb1, bb2, bb3, ss0, ss1, ss2, ss3;
                LDMX4(bb0, bb1, bb2, bb3, ab);
                LDMX4(ss0, ss1, ss2, ss3, ab + BSM_SPLIT);
                float* d0 = &acc[row][8 * p];
                float* d1 = &acc[row][8 * p + 4];
                MMA(d0, A0, bb0, bb1);
                MMA(d1, A0, bb2, bb3);
                MMA(d0, A0, ss0, ss1);
                MMA(d1, A0, ss2, ss3);
                MMA(d0, A1, bb0, bb1);
                MMA(d1, A1, bb2, bb3);
            }
        }
        A0 = nA0; A1 = nA1;
    }

    // ---- acc -> pre(sPre) with damping + bias ----
    float* sPre = (float*)((char*)sm + SPRE_B);
#pragma unroll
    for (int row = 0; row < 2; row++) {
        int y = y0 + row;
#pragma unroll
        for (int half = 0; half < 2; half++) {
            int co = w * 16 + (lane >> 2) + half * 8;
            float bco = bias[co];
            const float* zr = zin + ((b * CCH + co) * HH + y) * WW;
            float* sp = sPre + row * (CCH * 33) + co * 33;
#pragma unroll
            for (int nt = 0; nt < 4; nt++) {
                int x = nt * 8 + (lane & 3) * 2;
                float v0 = acc[row][nt * 4 + half * 2 + 0];
                float v1 = acc[row][nt * 4 + half * 2 + 1];
                sp[x]     = 0.1f * zr[x]     + 0.9f * (v0 + bco);
                sp[x + 1] = 0.1f * zr[x + 1] + 0.9f * (v1 + bco);
            }
        }
    }
    __syncthreads();

    // ---- softmax stats ----
    const int wg = tid >> 7;               // row
    const int wiw = (tid >> 5) & 3;        // warp within row-group
    float* pMax = (float*)((char*)sm + PMAX_B);
    float* pInv = (float*)((char*)sm + PINV_B);
    float* pRed = (float*)((char*)sm + PRED_B);
    float* sP = sPre + wg * (CCH * 33);

    for (int xx = wiw; xx < WW; xx += 4) {
        float m = -1e30f;
#pragma unroll
        for (int i = 0; i < 4; i++) m = fmaxf(m, sP[(lane + 32 * i) * 33 + xx]);
#pragma unroll
        for (int o = 16; o > 0; o >>= 1) m = fmaxf(m, __shfl_xor_sync(0xFFFFFFFF, m, o));
        float ss = 0.f;
#pragma unroll
        for (int i = 0; i < 4; i++) ss += __expf(sP[(lane + 32 * i) * 33 + xx] - m);
        ss = warpReduceSum(ss);
        if (lane == 0) { pMax[wg * 32 + xx] = m; pInv[wg * 32 + xx] = 1.0f / ss; }
    }
    __syncthreads();

    // ---- output + Gram/residual epilogue ----
    const int x = lane;
    const int y = y0 + wg;
    float dots[MMH] = {0.f, 0.f, 0.f, 0.f, 0.f};
    float resd = 0.f;
    float mx = pMax[wg * 32 + x], inv = pInv[wg * 32 + x];
    for (int c = wiw; c < CCH; c += 4) {
        int idx = ((b * CCH + c) * HH + y) * WW + x;
        float val = __expf(sP[c * 33 + x] - mx) * inv;
        fout[idx] = val;
        if (out2) out2[idx] = val;
        float gs = val - zin[idx];
#pragma unroll
        for (int j = 0; j < MMH; j++) {
            if (j < nact) {
                float gj = (j == slot) ? gs : (g_F[j][idx] - g_Z[j][idx]);
                dots[j] = fmaf(gs, gj, dots[j]);
            }
        }
        resd = fmaf(val, val, resd);
    }
#pragma unroll
    for (int j = 0; j < MMH + 1; j++) {
        bool act = (j < nact) || (j == MMH && do_res);
        float v = (j < MMH) ? dots[j] : resd;
        v = warpReduceSum(v);
        if (lane == 0) pRed[wg * 4 + wiw] = v;
        __syncthreads();
        if ((tid & 127) == 0 && act) {
            float t = pRed[wg * 4 + 0] + pRed[wg * 4 + 1] + pRed[wg * 4 + 2] + pRed[wg * 4 + 3];
            if (j < MMH) {
                atomicAdd(&g_S[b][slot][j], t);
                if (j != slot) atomicAdd(&g_S[b][j][slot], t);
            } else {
                atomicAdd(&g_resden, t);
            }
        }
        __syncthreads();
    }
}

// ---------------- host orchestration ----------------
extern "C" void kernel_launch(void* const* d_in, const int* in_sizes, int n_in,
                              void* d_out, int out_size) {
    const float* x = nullptr; const float* W = nullptr;
    const float* bias = nullptr; const int* mask = nullptr;
    for (int i = 0; i < n_in; i++) {
        switch (in_sizes[i]) {
            case 4194304: x    = (const float*)d_in[i]; break;
            case 147456:  W    = (const float*)d_in[i]; break;
            case 128:     bias = (const float*)d_in[i]; break;
            case 32768:   mask = (const int*)d_in[i];   break;
        }
    }
    float* out = (float*)d_out;

    cudaFuncSetAttribute(f_eval, cudaFuncAttributeMaxDynamicSharedMemorySize, SMEM_TOTAL);

    dim3 fgrid(HH / 2, BSZ);
    const int NB4 = NTOT / 4 / 256;

    prep_w<<<72, 256>>>(W);
    init_state<<<1, 256>>>();
    fill_z0<<<NB4, 256>>>();

    f_eval<<<fgrid, 256, SMEM_TOTAL>>>(0, 1, 1, 0, x, mask, bias);   // F0=f(z0), Z1=F0
    f_eval<<<fgrid, 256, SMEM_TOTAL>>>(1, -1, 2, 0, x, mask, bias);  // F1=f(F0)
    solve_k<<<1, 32>>>(2);

    for (int k = 2; k < 50; k++) {
        int s = k % MMH;
        int n = (k < MMH) ? k : MMH;
        int nactE = (k + 1 < MMH) ? (k + 1) : MMH;
        update_x<<<512, 256>>>(s, n);
        f_eval<<<fgrid, 256, SMEM_TOTAL>>>(s, -1, nactE, 1, x, mask, bias);
        check_solve<<<1, 32>>>(k);
    }

    final_copy<<<NB4, 256>>>(out);
    (void)out_size;
}

// round 6
// speedup vs baseline: 2.2624x; 1.0449x over previous
#include <cuda_runtime.h>
#include <cuda_bf16.h>
#include <math.h>
#include <stdint.h>

#define BSZ 32
#define CCH 128
#define HH  32
#define WW  32
#define HWP (HH*WW)
#define LL  (CCH*HWP)
#define NTOT (BSZ*LL)
#define MMH 5
#define LAMREG 1e-4f
#define TOLV 1e-5f

// ---------------- device state ----------------
__device__ float g_Fp[6][NTOT];       // F history, physical buffers (k mod 6)
__device__ float g_G[MMH][NTOT];      // G[j] = F[j] - X[j], logical slots
__device__ float g_X[NTOT];           // current iterate x (single buffer)
__device__ float g_S[BSZ][MMH][MMH];
__device__ float g_alpha[BSZ][MMH];
__device__ float g_resden;
__device__ int   g_flag;
__device__ int   g_outslot;           // PHYSICAL F index of last body
__device__ uint4 g_Wf0[72 * 256];     // A fragments big split
__device__ uint4 g_Wf1[72 * 256];     // A fragments small split

// ---------------- helpers ----------------
__device__ __forceinline__ uint32_t smem_u32(const void* p) {
    uint32_t a;
    asm("{ .reg .u64 t; cvta.to.shared.u64 t, %1; cvt.u32.u64 %0, t; }" : "=r"(a) : "l"(p));
    return a;
}
__device__ __forceinline__ uint32_t pk2(float a, float b) {
    __nv_bfloat162 t = __floats2bfloat162_rn(a, b);
    return *reinterpret_cast<uint32_t*>(&t);
}
__device__ __forceinline__ float warpReduceSum(float v) {
#pragma unroll
    for (int o = 16; o > 0; o >>= 1) v += __shfl_xor_sync(0xFFFFFFFF, v, o);
    return v;
}

#define LDMX4(r0, r1, r2, r3, addr) \
    asm volatile("ldmatrix.sync.aligned.m8n8.x4.shared.b16 {%0,%1,%2,%3}, [%4];" \
        : "=r"(r0), "=r"(r1), "=r"(r2), "=r"(r3) : "r"(addr))

#define MMA(d, a, b0_, b1_) \
    asm volatile("mma.sync.aligned.m16n8k16.row.col.f32.bf16.bf16.f32 " \
        "{%0,%1,%2,%3}, {%4,%5,%6,%7}, {%8,%9}, {%0,%1,%2,%3};" \
        : "+f"((d)[0]), "+f"((d)[1]), "+f"((d)[2]), "+f"((d)[3]) \
        : "r"((a).x), "r"((a).y), "r"((a).z), "r"((a).w), "r"(b0_), "r"(b1_))

// ---------------- smem layout (bytes) ----------------
#define BSM_ROWB   272
#define BSM_RSTR   (34 * BSM_ROWB)
#define BSM_SPLIT  (4 * BSM_RSTR)
#define BSM_BYTES  (2 * BSM_SPLIT)
#define SPRE_B     BSM_BYTES
#define PMAX_B     (SPRE_B + 33792)
#define PINV_B     (PMAX_B + 256)
#define PRED_B     (PINV_B + 256)
#define SMEM_TOTAL (PRED_B + 64)

// ---------------- small kernels ----------------
__global__ void prep_w(const float* __restrict__ W) {
    int t = blockIdx.x * 256 + threadIdx.x;
    if (t >= 72 * 256) return;
    int s = t >> 8, rem = t & 255, w = rem >> 5, l = rem & 31;
    int ky = s / 24, kx = (s / 8) % 3, cig = s & 7;
    int m0 = w * 16 + (l >> 2);
    int k0 = cig * 16 + (l & 3) * 2;
    uint32_t big[4], sml[4];
#pragma unroll
    for (int jc = 0; jc < 2; jc++)
#pragma unroll
        for (int jr = 0; jr < 2; jr++) {
            int reg = jc * 2 + jr;
            int co = m0 + jr * 8;
            int ci = k0 + jc * 8;
            float wa = W[((co * CCH + ci) * 3 + ky) * 3 + kx];
            float wb = W[((co * CCH + ci + 1) * 3 + ky) * 3 + kx];
            __nv_bfloat16 ba = __float2bfloat16(wa);
            __nv_bfloat16 bb = __float2bfloat16(wb);
            big[reg] = pk2(wa, wb);
            sml[reg] = pk2(wa - __bfloat162float(ba), wb - __bfloat162float(bb));
        }
    g_Wf0[t] = make_uint4(big[0], big[1], big[2], big[3]);
    g_Wf1[t] = make_uint4(sml[0], sml[1], sml[2], sml[3]);
}

__global__ void init_state() {
    int t = threadIdx.x;
    if (t == 0) { g_flag = 0; g_outslot = 0; g_resden = 0.f; }
    for (int i = t; i < BSZ * MMH * MMH; i += blockDim.x) ((float*)g_S)[i] = 0.f;
    for (int i = t; i < BSZ * MMH; i += blockDim.x) ((float*)g_alpha)[i] = 0.f;
}

__global__ void fill_z0() {
    int i = blockIdx.x * blockDim.x + threadIdx.x;
    const float v = 1.0f / 128.0f;
    ((float4*)g_X)[i] = make_float4(v, v, v, v);
}

__device__ __forceinline__ void solve_body(int b, int k) {
    int n = k < MMH ? k : MMH;
    int s = k % MMH;
    float A[6][6], rv[6];
    A[0][0] = 0.f;
    for (int j = 0; j < MMH; j++) {
        float a = (j < n) ? 1.f : 0.f;
        A[0][j + 1] = a; A[j + 1][0] = a;
    }
    for (int i = 0; i < MMH; i++)
        for (int j = 0; j < MMH; j++) {
            float v;
            if (i < n && j < n) v = g_S[b][i][j] + ((i == j) ? LAMREG : 0.f);
            else                v = (i == j) ? 1.f : 0.f;
            A[i + 1][j + 1] = v;
        }
    for (int i = 0; i < 6; i++) rv[i] = 0.f;
    rv[0] = 1.f;
    for (int c = 0; c < 6; c++) {
        int p = c; float mx = fabsf(A[c][c]);
        for (int r = c + 1; r < 6; r++) { float t = fabsf(A[r][c]); if (t > mx) { mx = t; p = r; } }
        if (p != c) {
            for (int q = c; q < 6; q++) { float t = A[c][q]; A[c][q] = A[p][q]; A[p][q] = t; }
            float t = rv[c]; rv[c] = rv[p]; rv[p] = t;
        }
        float inv = 1.f / A[c][c];
        for (int r = c + 1; r < 6; r++) {
            float f = A[r][c] * inv;
            if (f != 0.f) {
                for (int q = c + 1; q < 6; q++) A[r][q] -= f * A[c][q];
                rv[r] -= f * rv[c];
            }
        }
    }
    float xs[6];
    for (int c = 5; c >= 0; c--) {
        float t = rv[c];
        for (int q = c + 1; q < 6; q++) t -= A[c][q] * xs[q];
        xs[c] = t / A[c][c];
    }
    for (int j = 0; j < MMH; j++) g_alpha[b][j] = (j < n) ? xs[j + 1] : 0.f;
    for (int j = 0; j < MMH; j++) { g_S[b][s][j] = 0.f; g_S[b][j][s] = 0.f; }
}

__global__ void solve_k(int k) {
    if (g_flag) return;
    if (threadIdx.x < BSZ) solve_body(threadIdx.x, k);
}

__global__ void check_solve(int k, int pw) {
    if (g_flag) return;
    __shared__ int sconv;
    int b = threadIdx.x;
    int s = k % MMH;
    if (b == 0) {
        float rn = 0.f;
        for (int bb = 0; bb < BSZ; bb++) rn += g_S[bb][s][s];
        float res = sqrtf(rn) / (1e-5f + sqrtf(g_resden));
        g_outslot = pw;
        sconv = (res < TOLV) ? 1 : 0;
        g_resden = 0.f;
        if (sconv) g_flag = 1;
    }
    __syncthreads();
    if (sconv || k + 1 >= 50) return;
    if (b < BSZ) solve_body(b, k + 1);
}

__global__ void final_copy(float* __restrict__ out) {
    int i4 = blockIdx.x * blockDim.x + threadIdx.x;
    const float4* src = (const float4*)g_Fp[g_outslot];
    ((float4*)out)[i4] = src[i4];
}

// ---------------- fused f-evaluation (x-update + conv + softmax + Gram) ----------------
// Block = (y-pair, b), 8 warps. n>0: compute xnew = sum alpha_j F[pj] during staging,
// write center rows to g_X. n==0: input = (pin>=0 ? F[pin] : g_X).
__global__ void __launch_bounds__(256, 2)
f_eval(int slot, int n, int nact, int do_res, int pin,
       int p0, int p1, int p2, int p3, int p4, int pw,
       const float* __restrict__ xg, const int* __restrict__ maskg,
       const float* __restrict__ bias) {
    if (g_flag) return;
    extern __shared__ float sm[];
    const uint32_t smb = smem_u32(sm);
    const int tid = threadIdx.x;
    const int w = tid >> 5, lane = tid & 31;
    const int y0 = blockIdx.x * 2;
    const int b  = blockIdx.y;
    const float* zin = (n == 0 && pin >= 0) ? g_Fp[pin] : g_X;
    float* fout = g_Fp[pw];

    // ---- zero halo columns (xi = 0 and 33) ----
    for (int i = tid; i < 16 * (BSM_ROWB / 4); i += 256) {
        int word = i % (BSM_ROWB / 4);
        int rr = i / (BSM_ROWB / 4);
        int split = rr >> 3; int r = (rr >> 1) & 3; int xi = (rr & 1) ? 33 : 0;
        ((uint32_t*)((char*)sm + split * BSM_SPLIT + r * BSM_RSTR + xi * BSM_ROWB))[word] = 0;
    }

    // ---- stage B (+ fused x-update): warp w -> (r = w&3, cihalf = w>>2); lane = x ----
    {
        int r = w & 3, cihalf = w >> 2;
        int r_img = y0 + r - 1;
        char* dst0 = (char*)sm + r * BSM_RSTR + (lane + 1) * BSM_ROWB + cihalf * 128;
        char* dst1 = dst0 + BSM_SPLIT;
        if (r_img >= 0 && r_img < HH) {
            int m = maskg[(b * HH + r_img) * WW + lane];
            size_t bi = ((size_t)(b * CCH + cihalf * 64) * HH + r_img) * WW + lane;
            const float* xsrc = xg + bi;
            if (n > 0) {
                float a0 = g_alpha[b][0], a1 = g_alpha[b][1], a2 = g_alpha[b][2],
                      a3 = g_alpha[b][3], a4 = g_alpha[b][4];
                const float* f0 = g_Fp[p0] + bi;
                const float* f1 = g_Fp[p1] + bi;
                const float* f2 = g_Fp[p2] + bi;
                const float* f3 = g_Fp[p3] + bi;
                const float* f4 = g_Fp[p4] + bi;
                bool center = (r == 1) || (r == 2);
                float* zw = g_X + bi;
#pragma unroll 4
                for (int ci = 0; ci < 64; ci += 2) {
                    size_t o0 = (size_t)ci * HWP, o1 = o0 + (size_t)HWP;
                    float xa = a0 * f0[o0], xb = a0 * f0[o1];
                    if (n > 1) { xa = fmaf(a1, f1[o0], xa); xb = fmaf(a1, f1[o1], xb); }
                    if (n > 2) { xa = fmaf(a2, f2[o0], xa); xb = fmaf(a2, f2[o1], xb); }
                    if (n > 3) { xa = fmaf(a3, f3[o0], xa); xb = fmaf(a3, f3[o1], xb); }
                    if (n > 4) { xa = fmaf(a4, f4[o0], xa); xb = fmaf(a4, f4[o1], xb); }
                    if (center) { zw[o0] = xa; zw[o1] = xb; }
                    float va = m ? xsrc[o0] : xa;
                    float vb = m ? xsrc[o1] : xb;
                    __nv_bfloat16 ba = __float2bfloat16(va), bb2 = __float2bfloat16(vb);
                    *(uint32_t*)(dst0 + ci * 2) = pk2(va, vb);
                    *(uint32_t*)(dst1 + ci * 2) = pk2(va - __bfloat162float(ba), vb - __bfloat162float(bb2));
                }
            } else {
                const float* zsrc = zin + bi;
#pragma unroll 4
                for (int ci = 0; ci < 64; ci += 2) {
                    size_t o0 = (size_t)ci * HWP, o1 = o0 + (size_t)HWP;
                    float va = m ? xsrc[o0] : zsrc[o0];
                    float vb = m ? xsrc[o1] : zsrc[o1];
                    __nv_bfloat16 ba = __float2bfloat16(va), bb2 = __float2bfloat16(vb);
                    *(uint32_t*)(dst0 + ci * 2) = pk2(va, vb);
                    *(uint32_t*)(dst1 + ci * 2) = pk2(va - __bfloat162float(ba), vb - __bfloat162float(bb2));
                }
            }
        } else {
            for (int ci = 0; ci < 64; ci += 2) {
                *(uint32_t*)(dst0 + ci * 2) = 0;
                *(uint32_t*)(dst1 + ci * 2) = 0;
            }
        }
    }
    __syncthreads();

    // ---- conv: 72 k-steps, bf16x3, software-pipelined B fragments ----
    float acc[2][16];
#pragma unroll
    for (int r = 0; r < 2; r++)
#pragma unroll
        for (int i = 0; i < 16; i++) acc[r][i] = 0.f;

    const int fragidx = w * 32 + lane;
    const int mi = lane >> 3;
    const int khalf = mi & 1;
    const int qrow = mi >> 1;
    const uint4* pwA0 = g_Wf0 + fragidx;
    const uint4* pwA1 = g_Wf1 + fragidx;
    uint4 A0 = pwA0[0], A1 = pwA1[0];

    uint32_t abase[4];
#pragma unroll
    for (int c = 0; c < 4; c++)
        abase[c] = smb + (uint32_t)((c >> 1) * BSM_RSTR +
                   (((c & 1) * 2 + qrow) * 8 + (lane & 7)) * BSM_ROWB + khalf * 16);

    uint32_t Bb[2][4], Bs[2][4];
    LDMX4(Bb[0][0], Bb[0][1], Bb[0][2], Bb[0][3], abase[0]);
    LDMX4(Bs[0][0], Bs[0][1], Bs[0][2], Bs[0][3], abase[0] + BSM_SPLIT);

    uint32_t kb = 0;
    for (int ky = 0; ky < 3; ky++) {
        for (int kxc = 0; kxc < 3; kxc++) {
            uint32_t kbn = (kxc < 2) ? kb + BSM_ROWB : (uint32_t)((ky + 1) * BSM_RSTR);
#pragma unroll
            for (int cig = 0; cig < 8; cig++) {
                bool last = (ky == 2) && (kxc == 2) && (cig == 7);
                uint4 nA0, nA1;
                if (!last) { nA0 = pwA0[256]; nA1 = pwA1[256]; }
                pwA0 += 256; pwA1 += 256;
                uint32_t koff = kb + (uint32_t)(cig * 32);
                uint32_t nkoff = (cig < 7) ? (koff + 32) : kbn;
#pragma unroll
                for (int c = 0; c < 4; c++) {
                    uint32_t* cb = Bb[c & 1]; uint32_t* cs = Bs[c & 1];
                    uint32_t* nb = Bb[(c + 1) & 1]; uint32_t* ns = Bs[(c + 1) & 1];
                    if (c < 3) {
                        uint32_t ad = abase[c + 1] + koff;
                        LDMX4(nb[0], nb[1], nb[2], nb[3], ad);
                        LDMX4(ns[0], ns[1], ns[2], ns[3], ad + BSM_SPLIT);
                    } else if (!last) {
                        uint32_t ad = abase[0] + nkoff;
                        LDMX4(nb[0], nb[1], nb[2], nb[3], ad);
                        LDMX4(ns[0], ns[1], ns[2], ns[3], ad + BSM_SPLIT);
                    }
                    float* d0 = &acc[c >> 1][8 * (c & 1)];
                    float* d1 = d0 + 4;
                    MMA(d0, A0, cb[0], cb[1]);
                    MMA(d1, A0, cb[2], cb[3]);
                    MMA(d0, A0, cs[0], cs[1]);
                    MMA(d1, A0, cs[2], cs[3]);
                    MMA(d0, A1, cb[0], cb[1]);
                    MMA(d1, A1, cb[2], cb[3]);
                }
                if (!last) { A0 = nA0; A1 = nA1; }
            }
            kb = kbn;
        }
    }

    // ---- acc -> pre(sPre) with damping + bias ----
    float* sPre = (float*)((char*)sm + SPRE_B);
#pragma unroll
    for (int row = 0; row < 2; row++) {
        int y = y0 + row;
#pragma unroll
        for (int half = 0; half < 2; half++) {
            int co = w * 16 + (lane >> 2) + half * 8;
            float bco = bias[co];
            const float* zr = zin + ((b * CCH + co) * HH + y) * WW;
            float* sp = sPre + row * (CCH * 33) + co * 33;
#pragma unroll
            for (int nt = 0; nt < 4; nt++) {
                int x = nt * 8 + (lane & 3) * 2;
                float v0 = acc[row][nt * 4 + half * 2 + 0];
                float v1 = acc[row][nt * 4 + half * 2 + 1];
                sp[x]     = 0.1f * zr[x]     + 0.9f * (v0 + bco);
                sp[x + 1] = 0.1f * zr[x + 1] + 0.9f * (v1 + bco);
            }
        }
    }
    __syncthreads();

    // ---- softmax stats ----
    const int wg = tid >> 7;
    const int wiw = (tid >> 5) & 3;
    float* pMax = (float*)((char*)sm + PMAX_B);
    float* pInv = (float*)((char*)sm + PINV_B);
    float* pRed = (float*)((char*)sm + PRED_B);
    float* sP = sPre + wg * (CCH * 33);

    for (int xx = wiw; xx < WW; xx += 4) {
        float m = -1e30f;
#pragma unroll
        for (int i = 0; i < 4; i++) m = fmaxf(m, sP[(lane + 32 * i) * 33 + xx]);
#pragma unroll
        for (int o = 16; o > 0; o >>= 1) m = fmaxf(m, __shfl_xor_sync(0xFFFFFFFF, m, o));
        float ss = 0.f;
#pragma unroll
        for (int i = 0; i < 4; i++) ss += __expf(sP[(lane + 32 * i) * 33 + xx] - m);
        ss = warpReduceSum(ss);
        if (lane == 0) { pMax[wg * 32 + xx] = m; pInv[wg * 32 + xx] = 1.0f / ss; }
    }
    __syncthreads();

    // ---- output + Gram/residual epilogue (G arrays) ----
    const int x = lane;
    const int y = y0 + wg;
    float dots[MMH] = {0.f, 0.f, 0.f, 0.f, 0.f};
    float resd = 0.f;
    float mx = pMax[wg * 32 + x], inv = pInv[wg * 32 + x];
    float* gout = g_G[slot];
    for (int c = wiw; c < CCH; c += 4) {
        int idx = ((b * CCH + c) * HH + y) * WW + x;
        float val = __expf(sP[c * 33 + x] - mx) * inv;
        fout[idx] = val;
        float gs = val - zin[idx];
        gout[idx] = gs;
#pragma unroll
        for (int j = 0; j < MMH; j++) {
            if (j < nact) {
                float gj = (j == slot) ? gs : g_G[j][idx];
                dots[j] = fmaf(gs, gj, dots[j]);
            }
        }
        resd = fmaf(val, val, resd);
    }
#pragma unroll
    for (int j = 0; j < MMH + 1; j++) {
        bool act = (j < nact) || (j == MMH && do_res);
        float v = (j < MMH) ? dots[j] : resd;
        v = warpReduceSum(v);
        if (lane == 0) pRed[wg * 4 + wiw] = v;
        __syncthreads();
        if ((tid & 127) == 0 && act) {
            float t = pRed[wg * 4 + 0] + pRed[wg * 4 + 1] + pRed[wg * 4 + 2] + pRed[wg * 4 + 3];
            if (j < MMH) {
                atomicAdd(&g_S[b][slot][j], t);
                if (j != slot) atomicAdd(&g_S[b][j][slot], t);
            } else {
                atomicAdd(&g_resden, t);
            }
        }
        __syncthreads();
    }
}

// ---------------- host orchestration ----------------
extern "C" void kernel_launch(void* const* d_in, const int* in_sizes, int n_in,
                              void* d_out, int out_size) {
    const float* x = nullptr; const float* W = nullptr;
    const float* bias = nullptr; const int* mask = nullptr;
    for (int i = 0; i < n_in; i++) {
        switch (in_sizes[i]) {
            case 4194304: x    = (const float*)d_in[i]; break;
            case 147456:  W    = (const float*)d_in[i]; break;
            case 128:     bias = (const float*)d_in[i]; break;
            case 32768:   mask = (const int*)d_in[i];   break;
        }
    }
    float* out = (float*)d_out;

    cudaFuncSetAttribute(f_eval, cudaFuncAttributeMaxDynamicSharedMemorySize, SMEM_TOTAL);

    dim3 fgrid(HH / 2, BSZ);
    const int NB4 = NTOT / 4 / 256;

    prep_w<<<72, 256>>>(W);
    init_state<<<1, 256>>>();
    fill_z0<<<NB4, 256>>>();

    // k=0: F(phys0)=f(g_X); k=1: F(phys1)=f(F(phys0))
    f_eval<<<fgrid, 256, SMEM_TOTAL>>>(0, 0, 1, 0, -1, 0, 0, 0, 0, 0, 0, x, mask, bias);
    f_eval<<<fgrid, 256, SMEM_TOTAL>>>(1, 0, 2, 0,  0, 0, 0, 0, 0, 0, 1, x, mask, bias);
    solve_k<<<1, 32>>>(2);

    for (int k = 2; k < 50; k++) {
        int s = k % MMH;
        int n = (k < MMH) ? k : MMH;
        int nactE = (k + 1 < MMH) ? (k + 1) : MMH;
        int pw = k % 6;
        int pj[5];
        for (int j = 0; j < 5; j++) {
            if (j < n) {
                int kj = k - 1 - ((k - 1 - j) % 5);
                pj[j] = kj % 6;
            } else pj[j] = 0;
        }
        f_eval<<<fgrid, 256, SMEM_TOTAL>>>(s, n, nactE, 1, -1,
                                           pj[0], pj[1], pj[2], pj[3], pj[4], pw,
                                           x, mask, bias);
        check_solve<<<1, 32>>>(k, pw);
    }

    final_copy<<<NB4, 256>>>(out);
    (void)out_size;
}

// round 7
// speedup vs baseline: 2.5264x; 1.1167x over previous
#include <cuda_runtime.h>
#include <cuda_bf16.h>
#include <math.h>
#include <stdint.h>

#define BSZ 32
#define CCH 128
#define HH  32
#define WW  32
#define HWP (HH*WW)
#define LL  (CCH*HWP)
#define NTOT (BSZ*LL)
#define MMH 5
#define LAMREG 1e-4f
#define TOLV 1e-5f
#define NBLK 256

// ---------------- device state ----------------
__device__ float g_Fp[6][NTOT];       // F history, physical buffers (k mod 6)
__device__ float g_G[MMH][NTOT];      // G[j] = F[j] - X[j]
__device__ float g_X[NTOT];           // current iterate
__device__ float g_S[BSZ][MMH][MMH];
__device__ float g_alpha[BSZ][MMH];
__device__ float g_resden;
__device__ int   g_flag;
__device__ int   g_outslot;
__device__ uint4 g_Wf0[72 * 256];
__device__ uint4 g_Wf1[72 * 256];
__device__ unsigned g_barCnt;         // zero-init; returns to 0 after each barrier
__device__ unsigned g_barGen;         // monotonically increasing (relative sense)
__device__ int g_tileCtr;

// ---------------- helpers ----------------
__device__ __forceinline__ uint32_t smem_u32(const void* p) {
    uint32_t a;
    asm("{ .reg .u64 t; cvta.to.shared.u64 t, %1; cvt.u32.u64 %0, t; }" : "=r"(a) : "l"(p));
    return a;
}
__device__ __forceinline__ uint32_t pk2(float a, float b) {
    __nv_bfloat162 t = __floats2bfloat162_rn(a, b);
    return *reinterpret_cast<uint32_t*>(&t);
}
__device__ __forceinline__ float warpReduceSum(float v) {
#pragma unroll
    for (int o = 16; o > 0; o >>= 1) v += __shfl_xor_sync(0xFFFFFFFF, v, o);
    return v;
}

#define LDMX4(r0, r1, r2, r3, addr) \
    asm volatile("ldmatrix.sync.aligned.m8n8.x4.shared.b16 {%0,%1,%2,%3}, [%4];" \
        : "=r"(r0), "=r"(r1), "=r"(r2), "=r"(r3) : "r"(addr))

#define MMA(d, a, b0_, b1_) \
    asm volatile("mma.sync.aligned.m16n8k16.row.col.f32.bf16.bf16.f32 " \
        "{%0,%1,%2,%3}, {%4,%5,%6,%7}, {%8,%9}, {%0,%1,%2,%3};" \
        : "+f"((d)[0]), "+f"((d)[1]), "+f"((d)[2]), "+f"((d)[3]) \
        : "r"((a).x), "r"((a).y), "r"((a).z), "r"((a).w), "r"(b0_), "r"(b1_))

// ---------------- smem layout (bytes); sPre ALIASES the B tile area ----------------
#define BSM_ROWB   272
#define BSM_RSTR   (34 * BSM_ROWB)
#define BSM_SPLIT  (4 * BSM_RSTR)
#define BSM_BYTES  (2 * BSM_SPLIT)        // 73984
#define PMAX_B     BSM_BYTES              // 256 B
#define PINV_B     (PMAX_B + 256)
#define PRED_B     (PINV_B + 256)
#define SMEM_TOTAL (PRED_B + 64)          // 74624

// ---------------- grid barrier (all NBLK blocks guaranteed co-resident) ----------------
__device__ __forceinline__ void grid_sync() {
    __syncthreads();
    if (threadIdx.x == 0) {
        __threadfence();
        unsigned gen = *(volatile unsigned*)&g_barGen;
        if (atomicAdd(&g_barCnt, 1) == NBLK - 1) {
            g_barCnt = 0;
            __threadfence();
            atomicAdd(&g_barGen, 1);
        } else {
            while (*(volatile unsigned*)&g_barGen == gen) {}
            __threadfence();
        }
    }
    __syncthreads();
}

// ---------------- Anderson solve (per batch, 1 thread each) ----------------
__device__ void solve_body(int b, int k) {
    int n = k < MMH ? k : MMH;
    int s = k % MMH;
    float A[6][6], rv[6];
    A[0][0] = 0.f;
    for (int j = 0; j < MMH; j++) {
        float a = (j < n) ? 1.f : 0.f;
        A[0][j + 1] = a; A[j + 1][0] = a;
    }
    for (int i = 0; i < MMH; i++)
        for (int j = 0; j < MMH; j++) {
            float v;
            if (i < n && j < n) v = g_S[b][i][j] + ((i == j) ? LAMREG : 0.f);
            else                v = (i == j) ? 1.f : 0.f;
            A[i + 1][j + 1] = v;
        }
    for (int i = 0; i < 6; i++) rv[i] = 0.f;
    rv[0] = 1.f;
    for (int c = 0; c < 6; c++) {
        int p = c; float mx = fabsf(A[c][c]);
        for (int r = c + 1; r < 6; r++) { float t = fabsf(A[r][c]); if (t > mx) { mx = t; p = r; } }
        if (p != c) {
            for (int q = c; q < 6; q++) { float t = A[c][q]; A[c][q] = A[p][q]; A[p][q] = t; }
            float t = rv[c]; rv[c] = rv[p]; rv[p] = t;
        }
        float inv = 1.f / A[c][c];
        for (int r = c + 1; r < 6; r++) {
            float f = A[r][c] * inv;
            if (f != 0.f) {
                for (int q = c + 1; q < 6; q++) A[r][q] -= f * A[c][q];
                rv[r] -= f * rv[c];
            }
        }
    }
    float xs[6];
    for (int c = 5; c >= 0; c--) {
        float t = rv[c];
        for (int q = c + 1; q < 6; q++) t -= A[c][q] * xs[q];
        xs[c] = t / A[c][c];
    }
    for (int j = 0; j < MMH; j++) g_alpha[b][j] = (j < n) ? xs[j + 1] : 0.f;
    for (int j = 0; j < MMH; j++) { g_S[b][s][j] = 0.f; g_S[b][j][s] = 0.f; }
}

// ---------------- one f-evaluation pass over dynamically-grabbed tiles ----------------
__device__ __noinline__ void eval_pass(int slot, int n, int nact, int do_res, int pin, int pw,
                                       int p0, int p1, int p2, int p3, int p4,
                                       const float* __restrict__ xg,
                                       const int* __restrict__ maskg,
                                       const float* __restrict__ bias,
                                       float* sm) {
    const uint32_t smb = smem_u32(sm);
    const int tid = threadIdx.x;
    const int w = tid >> 5, lane = tid & 31;
    const float* zin = (n == 0 && pin >= 0) ? g_Fp[pin] : g_X;
    float* fout = g_Fp[pw];
    __shared__ int stile;

    for (;;) {
        if (tid == 0) stile = atomicAdd(&g_tileCtr, 1);
        __syncthreads();
        int tile = stile;
        if (tile >= 512) break;
        const int b = tile >> 4;
        const int y0 = (tile & 15) * 2;

        // ---- zero halo columns (xi = 0 and 33) ----
        for (int i = tid; i < 16 * (BSM_ROWB / 4); i += 256) {
            int word = i % (BSM_ROWB / 4);
            int rr = i / (BSM_ROWB / 4);
            int split = rr >> 3; int r = (rr >> 1) & 3; int xi = (rr & 1) ? 33 : 0;
            ((uint32_t*)((char*)sm + split * BSM_SPLIT + r * BSM_RSTR + xi * BSM_ROWB))[word] = 0;
        }

        // ---- stage B (+ fused x-update): warp w -> (r = w&3, cihalf = w>>2); lane = x ----
        {
            int r = w & 3, cihalf = w >> 2;
            int r_img = y0 + r - 1;
            char* dst0 = (char*)sm + r * BSM_RSTR + (lane + 1) * BSM_ROWB + cihalf * 128;
            char* dst1 = dst0 + BSM_SPLIT;
            if (r_img >= 0 && r_img < HH) {
                int m = maskg[(b * HH + r_img) * WW + lane];
                size_t bi = ((size_t)(b * CCH + cihalf * 64) * HH + r_img) * WW + lane;
                const float* xsrc = xg + bi;
                if (n > 0) {
                    float a0 = g_alpha[b][0], a1 = g_alpha[b][1], a2 = g_alpha[b][2],
                          a3 = g_alpha[b][3], a4 = g_alpha[b][4];
                    const float* f0 = g_Fp[p0] + bi;
                    const float* f1 = g_Fp[p1] + bi;
                    const float* f2 = g_Fp[p2] + bi;
                    const float* f3 = g_Fp[p3] + bi;
                    const float* f4 = g_Fp[p4] + bi;
                    bool center = (r == 1) || (r == 2);
                    float* zw = g_X + bi;
#pragma unroll 4
                    for (int ci = 0; ci < 64; ci += 2) {
                        size_t o0 = (size_t)ci * HWP, o1 = o0 + (size_t)HWP;
                        float xa = a0 * f0[o0], xb = a0 * f0[o1];
                        if (n > 1) { xa = fmaf(a1, f1[o0], xa); xb = fmaf(a1, f1[o1], xb); }
                        if (n > 2) { xa = fmaf(a2, f2[o0], xa); xb = fmaf(a2, f2[o1], xb); }
                        if (n > 3) { xa = fmaf(a3, f3[o0], xa); xb = fmaf(a3, f3[o1], xb); }
                        if (n > 4) { xa = fmaf(a4, f4[o0], xa); xb = fmaf(a4, f4[o1], xb); }
                        if (center) { zw[o0] = xa; zw[o1] = xb; }
                        float va = m ? xsrc[o0] : xa;
                        float vb = m ? xsrc[o1] : xb;
                        __nv_bfloat16 ba = __float2bfloat16(va), bb2 = __float2bfloat16(vb);
                        *(uint32_t*)(dst0 + ci * 2) = pk2(va, vb);
                        *(uint32_t*)(dst1 + ci * 2) = pk2(va - __bfloat162float(ba), vb - __bfloat162float(bb2));
                    }
                } else {
                    const float* zsrc = zin + bi;
#pragma unroll 4
                    for (int ci = 0; ci < 64; ci += 2) {
                        size_t o0 = (size_t)ci * HWP, o1 = o0 + (size_t)HWP;
                        float va = m ? xsrc[o0] : zsrc[o0];
                        float vb = m ? xsrc[o1] : zsrc[o1];
                        __nv_bfloat16 ba = __float2bfloat16(va), bb2 = __float2bfloat16(vb);
                        *(uint32_t*)(dst0 + ci * 2) = pk2(va, vb);
                        *(uint32_t*)(dst1 + ci * 2) = pk2(va - __bfloat162float(ba), vb - __bfloat162float(bb2));
                    }
                }
            } else {
                for (int ci = 0; ci < 64; ci += 2) {
                    *(uint32_t*)(dst0 + ci * 2) = 0;
                    *(uint32_t*)(dst1 + ci * 2) = 0;
                }
            }
        }
        __syncthreads();

        // ---- conv: 72 k-steps, bf16x3, software-pipelined ----
        float acc[2][16];
#pragma unroll
        for (int r = 0; r < 2; r++)
#pragma unroll
            for (int i = 0; i < 16; i++) acc[r][i] = 0.f;

        const int fragidx = w * 32 + lane;
        const int mi = lane >> 3;
        const int khalf = mi & 1;
        const int qrow = mi >> 1;
        const uint4* pwA0 = g_Wf0 + fragidx;
        const uint4* pwA1 = g_Wf1 + fragidx;
        uint4 A0 = pwA0[0], A1 = pwA1[0];

        uint32_t abase[4];
#pragma unroll
        for (int c = 0; c < 4; c++)
            abase[c] = smb + (uint32_t)((c >> 1) * BSM_RSTR +
                       (((c & 1) * 2 + qrow) * 8 + (lane & 7)) * BSM_ROWB + khalf * 16);

        uint32_t Bb[2][4], Bs[2][4];
        LDMX4(Bb[0][0], Bb[0][1], Bb[0][2], Bb[0][3], abase[0]);
        LDMX4(Bs[0][0], Bs[0][1], Bs[0][2], Bs[0][3], abase[0] + BSM_SPLIT);

        uint32_t kb = 0;
        for (int ky = 0; ky < 3; ky++) {
            for (int kxc = 0; kxc < 3; kxc++) {
                uint32_t kbn = (kxc < 2) ? kb + BSM_ROWB : (uint32_t)((ky + 1) * BSM_RSTR);
#pragma unroll
                for (int cig = 0; cig < 8; cig++) {
                    bool last = (ky == 2) && (kxc == 2) && (cig == 7);
                    uint4 nA0, nA1;
                    if (!last) { nA0 = pwA0[256]; nA1 = pwA1[256]; }
                    pwA0 += 256; pwA1 += 256;
                    uint32_t koff = kb + (uint32_t)(cig * 32);
                    uint32_t nkoff = (cig < 7) ? (koff + 32) : kbn;
#pragma unroll
                    for (int c = 0; c < 4; c++) {
                        uint32_t* cb = Bb[c & 1]; uint32_t* cs = Bs[c & 1];
                        uint32_t* nb = Bb[(c + 1) & 1]; uint32_t* ns = Bs[(c + 1) & 1];
                        if (c < 3) {
                            uint32_t ad = abase[c + 1] + koff;
                            LDMX4(nb[0], nb[1], nb[2], nb[3], ad);
                            LDMX4(ns[0], ns[1], ns[2], ns[3], ad + BSM_SPLIT);
                        } else if (!last) {
                            uint32_t ad = abase[0] + nkoff;
                            LDMX4(nb[0], nb[1], nb[2], nb[3], ad);
                            LDMX4(ns[0], ns[1], ns[2], ns[3], ad + BSM_SPLIT);
                        }
                        float* d0 = &acc[c >> 1][8 * (c & 1)];
                        float* d1 = d0 + 4;
                        MMA(d0, A0, cb[0], cb[1]);
                        MMA(d1, A0, cb[2], cb[3]);
                        MMA(d0, A0, cs[0], cs[1]);
                        MMA(d1, A0, cs[2], cs[3]);
                        MMA(d0, A1, cb[0], cb[1]);
                        MMA(d1, A1, cb[2], cb[3]);
                    }
                    if (!last) { A0 = nA0; A1 = nA1; }
                }
                kb = kbn;
            }
        }
        __syncthreads();   // Bsm dead; sPre aliases it below

        // ---- acc -> pre(sPre) with damping + bias ----
        float* sPre = sm;  // aliased over Bsm
#pragma unroll
        for (int row = 0; row < 2; row++) {
            int y = y0 + row;
#pragma unroll
            for (int half = 0; half < 2; half++) {
                int co = w * 16 + (lane >> 2) + half * 8;
                float bco = bias[co];
                const float* zr = zin + ((b * CCH + co) * HH + y) * WW;
                float* sp = sPre + row * (CCH * 33) + co * 33;
#pragma unroll
                for (int nt = 0; nt < 4; nt++) {
                    int x = nt * 8 + (lane & 3) * 2;
                    float v0 = acc[row][nt * 4 + half * 2 + 0];
                    float v1 = acc[row][nt * 4 + half * 2 + 1];
                    sp[x]     = 0.1f * zr[x]     + 0.9f * (v0 + bco);
                    sp[x + 1] = 0.1f * zr[x + 1] + 0.9f * (v1 + bco);
                }
            }
        }
        __syncthreads();

        // ---- softmax stats ----
        const int wg = tid >> 7;
        const int wiw = (tid >> 5) & 3;
        float* pMax = (float*)((char*)sm + PMAX_B);
        float* pInv = (float*)((char*)sm + PINV_B);
        float* pRed = (float*)((char*)sm + PRED_B);
        float* sP = sPre + wg * (CCH * 33);

        for (int xx = wiw; xx < WW; xx += 4) {
            float m = -1e30f;
#pragma unroll
            for (int i = 0; i < 4; i++) m = fmaxf(m, sP[(lane + 32 * i) * 33 + xx]);
#pragma unroll
            for (int o = 16; o > 0; o >>= 1) m = fmaxf(m, __shfl_xor_sync(0xFFFFFFFF, m, o));
            float ss = 0.f;
#pragma unroll
            for (int i = 0; i < 4; i++) ss += __expf(sP[(lane + 32 * i) * 33 + xx] - m);
            ss = warpReduceSum(ss);
            if (lane == 0) { pMax[wg * 32 + xx] = m; pInv[wg * 32 + xx] = 1.0f / ss; }
        }
        __syncthreads();

        // ---- output + Gram/residual epilogue ----
        const int x = lane;
        const int y = y0 + wg;
        float dots[MMH] = {0.f, 0.f, 0.f, 0.f, 0.f};
        float resd = 0.f;
        float mx = pMax[wg * 32 + x], inv = pInv[wg * 32 + x];
        float* gout = g_G[slot];
        for (int c = wiw; c < CCH; c += 4) {
            int idx = ((b * CCH + c) * HH + y) * WW + x;
            float val = __expf(sP[c * 33 + x] - mx) * inv;
            fout[idx] = val;
            float gs = val - zin[idx];
            gout[idx] = gs;
#pragma unroll
            for (int j = 0; j < MMH; j++) {
                if (j < nact) {
                    float gj = (j == slot) ? gs : g_G[j][idx];
                    dots[j] = fmaf(gs, gj, dots[j]);
                }
            }
            resd = fmaf(val, val, resd);
        }
#pragma unroll
        for (int j = 0; j < MMH + 1; j++) {
            bool act = (j < nact) || (j == MMH && do_res);
            float v = (j < MMH) ? dots[j] : resd;
            v = warpReduceSum(v);
            if (lane == 0) pRed[wg * 4 + wiw] = v;
            __syncthreads();
            if ((tid & 127) == 0 && act) {
                float t = pRed[wg * 4 + 0] + pRed[wg * 4 + 1] + pRed[wg * 4 + 2] + pRed[wg * 4 + 3];
                if (j < MMH) {
                    atomicAdd(&g_S[b][slot][j], t);
                    if (j != slot) atomicAdd(&g_S[b][j][slot], t);
                } else {
                    atomicAdd(&g_resden, t);
                }
            }
            __syncthreads();
        }
    }
}

// ---------------- the whole algorithm as ONE persistent kernel ----------------
__global__ void __launch_bounds__(256, 2)
mon_persistent(const float* __restrict__ xg, const int* __restrict__ maskg,
               const float* __restrict__ bias, const float* __restrict__ W,
               float* __restrict__ out) {
    extern __shared__ float sm[];
    __shared__ int s_conv;
    const int tid = threadIdx.x;
    const int bid = blockIdx.x;
    const int gt = bid * 256 + tid;

    // ---- init: weight fragments, z0, state ----
    if (gt < 72 * 256) {
        int s = gt >> 8, rem = gt & 255, w = rem >> 5, l = rem & 31;
        int ky = s / 24, kx = (s / 8) % 3, cig = s & 7;
        int m0 = w * 16 + (l >> 2);
        int k0 = cig * 16 + (l & 3) * 2;
        uint32_t big[4], sml[4];
#pragma unroll
        for (int jc = 0; jc < 2; jc++)
#pragma unroll
            for (int jr = 0; jr < 2; jr++) {
                int reg = jc * 2 + jr;
                int co = m0 + jr * 8;
                int ci = k0 + jc * 8;
                float wa = W[((co * CCH + ci) * 3 + ky) * 3 + kx];
                float wb = W[((co * CCH + ci + 1) * 3 + ky) * 3 + kx];
                __nv_bfloat16 ba = __float2bfloat16(wa);
                __nv_bfloat16 bb = __float2bfloat16(wb);
                big[reg] = pk2(wa, wb);
                sml[reg] = pk2(wa - __bfloat162float(ba), wb - __bfloat162float(bb));
            }
        g_Wf0[gt] = make_uint4(big[0], big[1], big[2], big[3]);
        g_Wf1[gt] = make_uint4(sml[0], sml[1], sml[2], sml[3]);
    }
    {
        const float v = 1.0f / 128.0f;
        float4 vv = make_float4(v, v, v, v);
        for (int i4 = gt; i4 < NTOT / 4; i4 += NBLK * 256) ((float4*)g_X)[i4] = vv;
    }
    if (gt < BSZ * MMH * MMH) ((float*)g_S)[gt] = 0.f;
    else if (gt < BSZ * MMH * MMH + BSZ * MMH) ((float*)g_alpha)[gt - BSZ * MMH * MMH] = 0.f;
    if (gt == 1000) { g_resden = 0.f; g_flag = 0; g_outslot = 0; g_tileCtr = 0; }
    grid_sync();

    // ---- k=0: F(p0)=f(g_X) ; k=1: F(p1)=f(F(p0)) ----
    eval_pass(0, 0, 1, 0, -1, 0, 0, 0, 0, 0, 0, xg, maskg, bias, sm);
    grid_sync();
    if (bid == 0 && tid == 0) g_tileCtr = 0;
    grid_sync();
    eval_pass(1, 0, 2, 0, 0, 1, 0, 0, 0, 0, 0, xg, maskg, bias, sm);
    grid_sync();
    if (bid == 0) {
        if (tid == 0) g_tileCtr = 0;
        if (tid < BSZ) solve_body(tid, 2);
    }
    grid_sync();

    // ---- main loop: zero cost when converged (break) ----
    for (int k = 2; k < 50; k++) {
        int s = k % MMH;
        int n = (k < MMH) ? k : MMH;
        int nact = (k + 1 < MMH) ? (k + 1) : MMH;
        int pw = k % 6;
        int pj[5];
#pragma unroll
        for (int j = 0; j < 5; j++) {
            int kj = k - 1 - ((k - 1 - j) % 5);
            pj[j] = kj % 6;
        }
        eval_pass(s, n, nact, 1, -1, pw, pj[0], pj[1], pj[2], pj[3], pj[4],
                  xg, maskg, bias, sm);
        grid_sync();
        if (bid == 0) {
            if (tid == 0) {
                float rn = 0.f;
                for (int bb = 0; bb < BSZ; bb++) rn += g_S[bb][s][s];
                float res = sqrtf(rn) / (1e-5f + sqrtf(g_resden));
                g_outslot = pw;
                int cv = (res < TOLV) ? 1 : 0;
                s_conv = cv;
                g_resden = 0.f;
                g_tileCtr = 0;
                if (cv) g_flag = 1;
            }
            __syncthreads();
            if (!s_conv && k + 1 < 50 && tid < BSZ) solve_body(tid, k + 1);
        }
        grid_sync();
        if (*(volatile int*)&g_flag) break;
    }

    // ---- final: out = F[outslot] ----
    {
        int sl = *(volatile int*)&g_outslot;
        const float4* src = (const float4*)g_Fp[sl];
        for (int i4 = gt; i4 < NTOT / 4; i4 += NBLK * 256) ((float4*)out)[i4] = src[i4];
    }
}

// ---------------- host ----------------
extern "C" void kernel_launch(void* const* d_in, const int* in_sizes, int n_in,
                              void* d_out, int out_size) {
    const float* x = nullptr; const float* W = nullptr;
    const float* bias = nullptr; const int* mask = nullptr;
    for (int i = 0; i < n_in; i++) {
        switch (in_sizes[i]) {
            case 4194304: x    = (const float*)d_in[i]; break;
            case 147456:  W    = (const float*)d_in[i]; break;
            case 128:     bias = (const float*)d_in[i]; break;
            case 32768:   mask = (const int*)d_in[i];   break;
        }
    }
    float* out = (float*)d_out;

    cudaFuncSetAttribute(mon_persistent, cudaFuncAttributeMaxDynamicSharedMemorySize, SMEM_TOTAL);
    mon_persistent<<<NBLK, 256, SMEM_TOTAL>>>(x, mask, bias, W, out);
    (void)out_size;
}